// round 5
// baseline (speedup 1.0000x reference)
#include <cuda_runtime.h>
#include <cstdint>

// GraphNetBlock — mma.sync tf32, v4:
//  * full-K SMEM residency: W(128x136) + A(256x132) resident, ZERO syncs inside
//    each GEMM stage (16 k8 uninterrupted), ~7 barriers/CTA total
//  * 512-thread CTA, 256 rows, 4x4 warp grid, 64x32 warp tiles (min crossbar)
//  * W prefetched into regs during mma, stored during epilogue
//  * proj trick from v3 (45 GFLOP total), red.v2 scatter, streaming stores

#define H 128
#define TE 256
#define THREADS 512

// smem float offsets
#define SW_OFF 0                  // W: 128 x 136 = 17408
#define HA_OFF 17408              // A/hidden: 256 x 132 = 33792
#define BIAS_F 51200              // 5 x 128
#define STAT_F 51840              // sum[256], sq[256]
#define SSR_F  52352              // sS[256], sR[256] ints
#define SMEM_FLOATS 52864
#define SMEM_BYTES (SMEM_FLOATS * 4)   // 211456

__device__ float g_acc[50000 * H];
__device__ float g_proj[50000 * 384];

__device__ __forceinline__ float to_tf32(float x) {
    unsigned u;
    asm("cvt.rna.tf32.f32 %0, %1;" : "=r"(u) : "f"(x));
    return __uint_as_float(u);
}
__device__ __forceinline__ void mma8(float c[4], const unsigned a[4], unsigned b0, unsigned b1) {
    asm volatile(
        "mma.sync.aligned.m16n8k8.row.col.f32.tf32.tf32.f32 "
        "{%0,%1,%2,%3}, {%4,%5,%6,%7}, {%8,%9}, {%0,%1,%2,%3};"
        : "+f"(c[0]), "+f"(c[1]), "+f"(c[2]), "+f"(c[3])
        : "r"(a[0]), "r"(a[1]), "r"(a[2]), "r"(a[3]), "r"(b0), "r"(b1));
}
__device__ __forceinline__ void red2(float* p, float a, float b) {
    asm volatile("red.global.add.v2.f32 [%0], {%1, %2};" :: "l"(p), "f"(a), "f"(b) : "memory");
}

// full K=128 GEMM: A rows (warp tile 64x32), W [k][n] stride 136
__device__ __forceinline__ void mma_K128(float c[16][4], const float* hA, const float* sW,
                                         int wm, int wn, int g, int tig) {
#pragma unroll
    for (int k8 = 0; k8 < 16; k8++) {
        unsigned b0[4], b1[4];
        const float* bp = sW + (k8 * 8 + tig) * 136 + wn * 32 + g;
#pragma unroll
        for (int jj = 0; jj < 4; jj++) {
            b0[jj] = __float_as_uint(bp[jj * 8]);
            b1[jj] = __float_as_uint(bp[4 * 136 + jj * 8]);
        }
#pragma unroll
        for (int mt = 0; mt < 4; mt++) {
            unsigned a[4];
            const float* ap = hA + (wm * 64 + mt * 16 + g) * 132 + k8 * 8 + tig;
            a[0] = __float_as_uint(ap[0]);
            a[1] = __float_as_uint(ap[8 * 132]);
            a[2] = __float_as_uint(ap[4]);
            a[3] = __float_as_uint(ap[8 * 132 + 4]);
#pragma unroll
            for (int jj = 0; jj < 4; jj++)
                mma8(c[mt * 4 + jj], a, b0[jj], b1[jj]);
        }
    }
}

__device__ __forceinline__ void ldg_W(float4 wv[8], const float* __restrict__ W, int tid) {
#pragma unroll
    for (int i = 0; i < 8; i++) {
        int idx4 = tid + i * THREADS;
        int kk = idx4 >> 5, n0 = (idx4 & 31) << 2;
        wv[i] = *(const float4*)(W + (size_t)kk * H + n0);
    }
}
__device__ __forceinline__ void sts_W(const float4 wv[8], float* sW, int tid) {
#pragma unroll
    for (int i = 0; i < 8; i++) {
        int idx4 = tid + i * THREADS;
        int kk = idx4 >> 5, n0 = (idx4 & 31) << 2;
        *(float4*)(sW + kk * 136 + n0) =
            make_float4(to_tf32(wv[i].x), to_tf32(wv[i].y), to_tf32(wv[i].z), to_tf32(wv[i].w));
    }
}
__device__ __forceinline__ void zero_c(float c[16][4]) {
#pragma unroll
    for (int j = 0; j < 16; j++)
#pragma unroll
        for (int i = 0; i < 4; i++) c[j][i] = 0.f;
}

// ================= unified kernel: MODE 0=proj, 1=edge, 2=node =================
template <int MODE>
__global__ void __launch_bounds__(THREADS, 1)
gnb_kernel(const int* __restrict__ send, const int* __restrict__ recv,
           const float* __restrict__ nodef, const float* __restrict__ resid,
           float* __restrict__ acc, float* __restrict__ proj,
           const float* __restrict__ Wa, const float* __restrict__ Wb,
           const float* __restrict__ Wc,
           const float* __restrict__ pb0, const float* __restrict__ pb1,
           const float* __restrict__ pb2,
           const float* __restrict__ gam, const float* __restrict__ bet,
           float* __restrict__ out, int rows) {
    extern __shared__ float sm[];
    float* sW = sm + SW_OFF;
    float* hA = sm + HA_OFF;
    float* sSum = sm + STAT_F;
    float* sSq  = sm + STAT_F + 256;
    int* sS = (int*)(sm + SSR_F);
    int* sR = (int*)(sm + SSR_F + 256);

    const int tid = threadIdx.x, lane = tid & 31, warp = tid >> 5;
    const int g = lane >> 2, tig = lane & 3;
    const int wm = warp >> 2, wn = warp & 3;
    const int base = blockIdx.x * TE;
    const int nvalid = min(TE, rows - base);

    // ---- prologue ----
    if (MODE != 0 && tid < H) {
        sm[BIAS_F + 0 * H + tid] = pb0[tid];
        sm[BIAS_F + 1 * H + tid] = pb1[tid];
        sm[BIAS_F + 2 * H + tid] = pb2[tid];
        sm[BIAS_F + 3 * H + tid] = gam[tid];
        sm[BIAS_F + 4 * H + tid] = bet[tid];
    }
    if (tid < 256) { sSum[tid] = 0.f; sSq[tid] = 0.f; }
    if (MODE == 1 && tid < TE) {
        int e = min(base + tid, rows - 1);
        sS[tid] = send[e];
        sR[tid] = recv[e];
    }
    {
        float4 wv[8];
        ldg_W(wv, Wa, tid);
        // stage A tile (256 x 128, tf32, stride 132)
#pragma unroll
        for (int i = 0; i < 16; i++) {
            int idx4 = tid + (i << 9);
            int r = idx4 >> 5;
            int c4 = (idx4 & 31) << 2;
            int rg = min(base + r, rows - 1);
            float4 v;
            if (MODE == 0) {
                v = *(const float4*)(nodef + (size_t)rg * H + c4);
            } else if (MODE == 1) {
                v = *(const float4*)(resid + (size_t)rg * H + c4);
            } else {
                float4* zp = (float4*)(acc + (size_t)rg * H + c4);
                v = *zp;
                if (base + r < rows) *zp = make_float4(0.f, 0.f, 0.f, 0.f);
            }
            *(float4*)(hA + r * 132 + c4) =
                make_float4(to_tf32(v.x), to_tf32(v.y), to_tf32(v.z), to_tf32(v.w));
        }
        sts_W(wv, sW, tid);
    }
    __syncthreads();

    float c[16][4];

#pragma unroll 1
    for (int s = 0; s < 3; s++) {
        zero_c(c);
        mma_K128(c, hA, sW, wm, wn, g, tig);

        float4 wv[8];
        if (s < 2) ldg_W(wv, (s == 0) ? Wb : Wc, tid);
        __syncthreads();   // all mma done reading sW + hA

        // ================= epilogues =================
        if (MODE == 0) {
            // store raw to proj col-block s
#pragma unroll
            for (int mt = 0; mt < 4; mt++)
#pragma unroll
                for (int h = 0; h < 2; h++) {
                    int r = wm * 64 + mt * 16 + g + 8 * h;
                    if (r < nvalid) {
                        float* p = proj + (size_t)(base + r) * 384 + s * 128;
#pragma unroll
                        for (int jj = 0; jj < 4; jj++) {
                            int n0 = wn * 32 + jj * 8 + 2 * tig;
                            *(float2*)(p + n0) =
                                make_float2(c[mt * 4 + jj][2 * h], c[mt * 4 + jj][2 * h + 1]);
                        }
                    }
                }
        } else if (s == 0) {
            const float* bS = sm + BIAS_F;
#pragma unroll
            for (int mt = 0; mt < 4; mt++)
#pragma unroll
                for (int h = 0; h < 2; h++) {
                    int r = wm * 64 + mt * 16 + g + 8 * h;
                    const float* sp;
                    const float* rp;
                    if (MODE == 1) {
                        sp = proj + (size_t)sS[r] * 384;
                        rp = proj + (size_t)sR[r] * 384 + 128;
                    } else {
                        sp = proj + (size_t)min(base + r, rows - 1) * 384 + 256;
                        rp = nullptr;
                    }
#pragma unroll
                    for (int jj = 0; jj < 4; jj++) {
                        int n0 = wn * 32 + jj * 8 + 2 * tig;
                        float2 av = *(const float2*)(sp + n0);
                        float v0 = c[mt * 4 + jj][2 * h] + av.x + bS[n0];
                        float v1 = c[mt * 4 + jj][2 * h + 1] + av.y + bS[n0 + 1];
                        if (MODE == 1) {
                            float2 bv = *(const float2*)(rp + n0);
                            v0 += bv.x;
                            v1 += bv.y;
                        }
                        *(float2*)(hA + r * 132 + n0) =
                            make_float2(to_tf32(fmaxf(v0, 0.f)), to_tf32(fmaxf(v1, 0.f)));
                    }
                }
        } else if (s == 1) {
            const float* bS = sm + BIAS_F + H;
#pragma unroll
            for (int mt = 0; mt < 4; mt++)
#pragma unroll
                for (int h = 0; h < 2; h++) {
                    int r = wm * 64 + mt * 16 + g + 8 * h;
#pragma unroll
                    for (int jj = 0; jj < 4; jj++) {
                        int n0 = wn * 32 + jj * 8 + 2 * tig;
                        float v0 = c[mt * 4 + jj][2 * h] + bS[n0];
                        float v1 = c[mt * 4 + jj][2 * h + 1] + bS[n0 + 1];
                        *(float2*)(hA + r * 132 + n0) =
                            make_float2(to_tf32(fmaxf(v0, 0.f)), to_tf32(fmaxf(v1, 0.f)));
                    }
                }
        } else {
            // ---- final: bias + cross-warp LN stats + residual + scatter ----
            const float* bS = sm + BIAS_F + 2 * H;
            float ps[4][2], pq[4][2];
#pragma unroll
            for (int mt = 0; mt < 4; mt++)
#pragma unroll
                for (int h = 0; h < 2; h++) {
                    float sacc = 0.f, qacc = 0.f;
#pragma unroll
                    for (int jj = 0; jj < 4; jj++) {
                        int n0 = wn * 32 + jj * 8 + 2 * tig;
                        float v0 = c[mt * 4 + jj][2 * h] + bS[n0];
                        float v1 = c[mt * 4 + jj][2 * h + 1] + bS[n0 + 1];
                        c[mt * 4 + jj][2 * h] = v0;
                        c[mt * 4 + jj][2 * h + 1] = v1;
                        sacc += v0 + v1;
                        qacc += v0 * v0 + v1 * v1;
                    }
                    ps[mt][h] = sacc;
                    pq[mt][h] = qacc;
                }
#pragma unroll
            for (int m = 1; m < 4; m <<= 1)
#pragma unroll
                for (int mt = 0; mt < 4; mt++)
#pragma unroll
                    for (int h = 0; h < 2; h++) {
                        ps[mt][h] += __shfl_xor_sync(0xffffffffu, ps[mt][h], m);
                        pq[mt][h] += __shfl_xor_sync(0xffffffffu, pq[mt][h], m);
                    }
            if (tig == 0) {
#pragma unroll
                for (int mt = 0; mt < 4; mt++)
#pragma unroll
                    for (int h = 0; h < 2; h++) {
                        int r = wm * 64 + mt * 16 + g + 8 * h;
                        atomicAdd(&sSum[r], ps[mt][h]);
                        atomicAdd(&sSq[r], pq[mt][h]);
                    }
            }
            __syncthreads();
            const float* gS = sm + BIAS_F + 3 * H;
            const float* eS = sm + BIAS_F + 4 * H;
#pragma unroll
            for (int mt = 0; mt < 4; mt++)
#pragma unroll
                for (int h = 0; h < 2; h++) {
                    int r = wm * 64 + mt * 16 + g + 8 * h;
                    if (r >= nvalid) continue;
                    float mu = sSum[r] * (1.f / H);
                    float rs = rsqrtf(sSq[r] * (1.f / H) - mu * mu + 1e-5f);
                    size_t ro = (size_t)(base + r) * H;
                    int rc = (MODE == 1) ? sR[r] : 0;
#pragma unroll
                    for (int jj = 0; jj < 4; jj++) {
                        int n0 = wn * 32 + jj * 8 + 2 * tig;
                        float y0 = (c[mt * 4 + jj][2 * h] - mu) * rs * gS[n0] + eS[n0];
                        float y1 = (c[mt * 4 + jj][2 * h + 1] - mu) * rs * gS[n0 + 1] + eS[n0 + 1];
                        float2 rf = *(const float2*)(resid + ro + n0);
                        __stcs((float2*)(out + ro + n0), make_float2(y0 + rf.x, y1 + rf.y));
                        if (MODE == 1) red2(&acc[(size_t)rc * H + n0], y0, y1);
                    }
                }
        }

        if (s < 2) {
            sts_W(wv, sW, tid);
            __syncthreads();   // W(s+1) staged + hA updated
        }
    }
}

// ============================ LAUNCH ============================
extern "C" void kernel_launch(void* const* d_in, const int* in_sizes, int n_in,
                              void* d_out, int out_size) {
    const int*   senders   = (const int*)d_in[0];
    const int*   receivers = (const int*)d_in[1];
    const float* nodef     = (const float*)d_in[2];
    const float* edgef     = (const float*)d_in[3];
    const float* eW0 = (const float*)d_in[4];
    const float* eb0 = (const float*)d_in[5];
    const float* eW1 = (const float*)d_in[6];
    const float* eb1 = (const float*)d_in[7];
    const float* eW2 = (const float*)d_in[8];
    const float* eb2 = (const float*)d_in[9];
    const float* eg  = (const float*)d_in[10];
    const float* ebeta = (const float*)d_in[11];
    const float* nW0 = (const float*)d_in[12];
    const float* nb0 = (const float*)d_in[13];
    const float* nW1 = (const float*)d_in[14];
    const float* nb1 = (const float*)d_in[15];
    const float* nW2 = (const float*)d_in[16];
    const float* nb2 = (const float*)d_in[17];
    const float* ng  = (const float*)d_in[18];
    const float* nbeta = (const float*)d_in[19];

    int E = in_sizes[1];
    int N = in_sizes[2] / H;

    float* out_node = (float*)d_out;
    float* out_edge = out_node + (size_t)N * H;

    float *acc = nullptr, *proj = nullptr;
    cudaGetSymbolAddress((void**)&acc, g_acc);
    cudaGetSymbolAddress((void**)&proj, g_proj);

    cudaFuncSetAttribute(gnb_kernel<0>, cudaFuncAttributeMaxDynamicSharedMemorySize, SMEM_BYTES);
    cudaFuncSetAttribute(gnb_kernel<1>, cudaFuncAttributeMaxDynamicSharedMemorySize, SMEM_BYTES);
    cudaFuncSetAttribute(gnb_kernel<2>, cudaFuncAttributeMaxDynamicSharedMemorySize, SMEM_BYTES);

    int ngrid = (N + TE - 1) / TE;
    int egrid = (E + TE - 1) / TE;

    // proj: P = nodef @ [eW0_send | eW0_recv | nW0_top]
    gnb_kernel<0><<<ngrid, THREADS, SMEM_BYTES>>>(
        nullptr, nullptr, nodef, nullptr, acc, proj,
        eW0, eW0 + (size_t)128 * H, nW0,
        eb0, eb0, eb0, eg, ebeta, nullptr, N);

    // edge MLP: ef @ eW0_bot (+gathered P) -> eW1 -> eW2 -> LN -> scatter
    gnb_kernel<1><<<egrid, THREADS, SMEM_BYTES>>>(
        senders, receivers, nodef, edgef, acc, proj,
        eW0 + (size_t)256 * H, eW1, eW2,
        eb0, eb1, eb2, eg, ebeta, out_edge, E);

    // node MLP: acc @ nW0_bot (+P nf-block) -> nW1 -> nW2 -> LN
    gnb_kernel<2><<<ngrid, THREADS, SMEM_BYTES>>>(
        nullptr, nullptr, nodef, nodef, acc, proj,
        nW0 + (size_t)128 * H, nW1, nW2,
        nb0, nb1, nb2, ng, nbeta, out_node, N);
}

// round 7
// speedup vs baseline: 1.5627x; 1.5627x over previous
#include <cuda_runtime.h>
#include <cstdint>

// GraphNetBlock — mma.sync tf32, v5 (resubmit after infra failure):
//  * proj trick: P = nodef @ [eW0_s | eW0_r | nW0_top] once per node (45 GFLOP)
//  * 128-row CTAs, 256 threads, 2 CTAs/SM (inter-CTA overlap hides epilogues)
//  * 4x2 warp grid, 32x64 warp tiles: 1.5 LDS-issue/mma (was 2.25)
//  * W plain [k][n] stride-136 smem, register-prefetch next chunk under mma
//  * red.v2 scatter, streaming stores

#define H 128
#define TE 128
#define KC 32
#define THREADS 256

// float offsets in dynamic smem
#define SW_OFF 0                 // 2 x (32 x 136) = 8704
#define HA_OFF 8704              // A/hidden: 128 x 132 = 16896
#define BIAS_F 25600             // 5 x 128
#define STAT_F 26240             // sum[128], sq[128]
#define SSR_F  26496             // sS[128], sR[128] ints
#define SMEM_FLOATS 26752
#define SMEM_BYTES (SMEM_FLOATS * 4)   // 107008

__device__ float g_acc[50000 * H];
__device__ float g_proj[50000 * 384];

__device__ __forceinline__ float to_tf32(float x) {
    unsigned u;
    asm("cvt.rna.tf32.f32 %0, %1;" : "=r"(u) : "f"(x));
    return __uint_as_float(u);
}
__device__ __forceinline__ void mma8(float c[4], const unsigned a[4], unsigned b0, unsigned b1) {
    asm volatile(
        "mma.sync.aligned.m16n8k8.row.col.f32.tf32.tf32.f32 "
        "{%0,%1,%2,%3}, {%4,%5,%6,%7}, {%8,%9}, {%0,%1,%2,%3};"
        : "+f"(c[0]), "+f"(c[1]), "+f"(c[2]), "+f"(c[3])
        : "r"(a[0]), "r"(a[1]), "r"(a[2]), "r"(a[3]), "r"(b0), "r"(b1));
}
__device__ __forceinline__ void red2(float* p, float a, float b) {
    asm volatile("red.global.add.v2.f32 [%0], {%1, %2};" :: "l"(p), "f"(a), "f"(b) : "memory");
}

// one staged 32-k chunk: A stride 132 (rows wm*32..+32), W stride 136 (cols wn*64..+64)
__device__ __forceinline__ void mma_chunk(float c[16][4], const float* As, const float* Ws,
                                          int wm, int wn, int g, int tig) {
#pragma unroll
    for (int k8 = 0; k8 < 4; k8++) {
        unsigned b0[8], b1[8];
        const float* bp = Ws + (k8 * 8 + tig) * 136 + wn * 64 + g;
#pragma unroll
        for (int jj = 0; jj < 8; jj++) {
            b0[jj] = __float_as_uint(bp[jj * 8]);
            b1[jj] = __float_as_uint(bp[4 * 136 + jj * 8]);
        }
#pragma unroll
        for (int mt = 0; mt < 2; mt++) {
            unsigned a[4];
            const float* ap = As + (wm * 32 + mt * 16 + g) * 132 + k8 * 8 + tig;
            a[0] = __float_as_uint(ap[0]);
            a[1] = __float_as_uint(ap[8 * 132]);
            a[2] = __float_as_uint(ap[4]);
            a[3] = __float_as_uint(ap[8 * 132 + 4]);
#pragma unroll
            for (int jj = 0; jj < 8; jj++)
                mma8(c[mt * 8 + jj], a, b0[jj], b1[jj]);
        }
    }
}

__device__ __forceinline__ void ldg_W(float4 wv[4], const float* __restrict__ W, int kt, int tid) {
#pragma unroll
    for (int i = 0; i < 4; i++) {
        int idx4 = tid + (i << 8);
        int kk = idx4 >> 5, n0 = (idx4 & 31) << 2;
        wv[i] = *(const float4*)(W + (size_t)(kt + kk) * H + n0);
    }
}
__device__ __forceinline__ void sts_W(const float4 wv[4], float* sWd, int tid) {
#pragma unroll
    for (int i = 0; i < 4; i++) {
        int idx4 = tid + (i << 8);
        int kk = idx4 >> 5, n0 = (idx4 & 31) << 2;
        *(float4*)(sWd + kk * 136 + n0) =
            make_float4(to_tf32(wv[i].x), to_tf32(wv[i].y), to_tf32(wv[i].z), to_tf32(wv[i].w));
    }
}
__device__ __forceinline__ void zero_c(float c[16][4]) {
#pragma unroll
    for (int j = 0; j < 16; j++)
#pragma unroll
        for (int i = 0; i < 4; i++) c[j][i] = 0.f;
}

// ================= unified kernel: MODE 0=proj, 1=edge, 2=node =================
template <int MODE>
__global__ void __launch_bounds__(THREADS, 2)
gnb_kernel(const int* __restrict__ send, const int* __restrict__ recv,
           const float* __restrict__ nodef, const float* __restrict__ resid,
           float* __restrict__ acc, float* __restrict__ proj,
           const float* __restrict__ Wa, const float* __restrict__ Wb,
           const float* __restrict__ Wc,
           const float* __restrict__ pb0, const float* __restrict__ pb1,
           const float* __restrict__ pb2,
           const float* __restrict__ gam, const float* __restrict__ bet,
           float* __restrict__ out, int rows) {
    extern __shared__ float sm[];
    float* sW = sm + SW_OFF;
    float* hA = sm + HA_OFF;
    float* sSum = sm + STAT_F;
    float* sSq  = sm + STAT_F + 128;
    int* sS = (int*)(sm + SSR_F);
    int* sR = (int*)(sm + SSR_F + 128);

    const int tid = threadIdx.x, lane = tid & 31, warp = tid >> 5;
    const int g = lane >> 2, tig = lane & 3;
    const int wm = warp >> 1, wn = warp & 1;
    const int base = blockIdx.x * TE;
    const int nvalid = min(TE, rows - base);

    // ---- prologue ----
    if (MODE != 0 && tid < H) {
        sm[BIAS_F + 0 * H + tid] = pb0[tid];
        sm[BIAS_F + 1 * H + tid] = pb1[tid];
        sm[BIAS_F + 2 * H + tid] = pb2[tid];
        sm[BIAS_F + 3 * H + tid] = gam[tid];
        sm[BIAS_F + 4 * H + tid] = bet[tid];
    }
    if (MODE != 0 && tid < 128) { sSum[tid] = 0.f; sSq[tid] = 0.f; }
    if (MODE == 1 && tid < TE) {
        int e = min(base + tid, rows - 1);
        sS[tid] = send[e];
        sR[tid] = recv[e];
    }
    // stage A tile (128 x 128, tf32, stride 132)
#pragma unroll
    for (int i = 0; i < 16; i++) {
        int idx4 = tid + (i << 8);
        int r = idx4 >> 5;
        int c4 = (idx4 & 31) << 2;
        int rg = min(base + r, rows - 1);
        float4 v;
        if (MODE == 0) {
            v = *(const float4*)(nodef + (size_t)rg * H + c4);
        } else if (MODE == 1) {
            v = *(const float4*)(resid + (size_t)rg * H + c4);
        } else {
            float4* zp = (float4*)(acc + (size_t)rg * H + c4);
            v = *zp;
            if (base + r < rows) *zp = make_float4(0.f, 0.f, 0.f, 0.f);
        }
        *(float4*)(hA + r * 132 + c4) =
            make_float4(to_tf32(v.x), to_tf32(v.y), to_tf32(v.z), to_tf32(v.w));
    }

    float c[16][4];

#pragma unroll 1
    for (int s = 0; s < 3; s++) {
        const float* W = (s == 0) ? Wa : (s == 1) ? Wb : Wc;
        zero_c(c);
        float4 wv[4];
        ldg_W(wv, W, 0, tid);
        sts_W(wv, sW, tid);
        __syncthreads();   // W chunk0 staged; hA writes (prologue/epilogue) visible
#pragma unroll 1
        for (int t = 0; t < 4; t++) {
            if (t < 3) ldg_W(wv, W, (t + 1) * KC, tid);
            mma_chunk(c, hA + t * KC, sW + (t & 1) * 4352, wm, wn, g, tig);
            if (t < 3) sts_W(wv, sW + ((t + 1) & 1) * 4352, tid);
            __syncthreads();
        }

        // ================= epilogues =================
        if (MODE == 0) {
            // store raw to proj col-block s (A tile unchanged: all stages read nodef)
#pragma unroll
            for (int mt = 0; mt < 2; mt++)
#pragma unroll
                for (int h = 0; h < 2; h++) {
                    int r = wm * 32 + mt * 16 + g + 8 * h;
                    if (r < nvalid) {
                        float* p = proj + (size_t)(base + r) * 384 + s * 128;
#pragma unroll
                        for (int jj = 0; jj < 8; jj++) {
                            int n0 = wn * 64 + jj * 8 + 2 * tig;
                            *(float2*)(p + n0) =
                                make_float2(c[mt * 8 + jj][2 * h], c[mt * 8 + jj][2 * h + 1]);
                        }
                    }
                }
        } else if (s == 0) {
            const float* bS = sm + BIAS_F;
#pragma unroll
            for (int mt = 0; mt < 2; mt++)
#pragma unroll
                for (int h = 0; h < 2; h++) {
                    int r = wm * 32 + mt * 16 + g + 8 * h;
                    const float* sp;
                    const float* rp = nullptr;
                    if (MODE == 1) {
                        sp = proj + (size_t)sS[r] * 384;
                        rp = proj + (size_t)sR[r] * 384 + 128;
                    } else {
                        sp = proj + (size_t)min(base + r, rows - 1) * 384 + 256;
                    }
#pragma unroll
                    for (int jj = 0; jj < 8; jj++) {
                        int n0 = wn * 64 + jj * 8 + 2 * tig;
                        float2 av = *(const float2*)(sp + n0);
                        float v0 = c[mt * 8 + jj][2 * h] + av.x + bS[n0];
                        float v1 = c[mt * 8 + jj][2 * h + 1] + av.y + bS[n0 + 1];
                        if (MODE == 1) {
                            float2 bv = *(const float2*)(rp + n0);
                            v0 += bv.x;
                            v1 += bv.y;
                        }
                        *(float2*)(hA + r * 132 + n0) =
                            make_float2(to_tf32(fmaxf(v0, 0.f)), to_tf32(fmaxf(v1, 0.f)));
                    }
                }
        } else if (s == 1) {
            const float* bS = sm + BIAS_F + H;
#pragma unroll
            for (int mt = 0; mt < 2; mt++)
#pragma unroll
                for (int h = 0; h < 2; h++) {
                    int r = wm * 32 + mt * 16 + g + 8 * h;
#pragma unroll
                    for (int jj = 0; jj < 8; jj++) {
                        int n0 = wn * 64 + jj * 8 + 2 * tig;
                        float v0 = c[mt * 8 + jj][2 * h] + bS[n0];
                        float v1 = c[mt * 8 + jj][2 * h + 1] + bS[n0 + 1];
                        *(float2*)(hA + r * 132 + n0) =
                            make_float2(to_tf32(fmaxf(v0, 0.f)), to_tf32(fmaxf(v1, 0.f)));
                    }
                }
        } else {
            // ---- final: bias + LN (2-warp row combine) + residual + scatter ----
            const float* bS = sm + BIAS_F + 2 * H;
            float ps[2][2], pq[2][2];
#pragma unroll
            for (int mt = 0; mt < 2; mt++)
#pragma unroll
                for (int h = 0; h < 2; h++) {
                    float sacc = 0.f, qacc = 0.f;
#pragma unroll
                    for (int jj = 0; jj < 8; jj++) {
                        int n0 = wn * 64 + jj * 8 + 2 * tig;
                        float v0 = c[mt * 8 + jj][2 * h] + bS[n0];
                        float v1 = c[mt * 8 + jj][2 * h + 1] + bS[n0 + 1];
                        c[mt * 8 + jj][2 * h] = v0;
                        c[mt * 8 + jj][2 * h + 1] = v1;
                        sacc += v0 + v1;
                        qacc += v0 * v0 + v1 * v1;
                    }
                    ps[mt][h] = sacc;
                    pq[mt][h] = qacc;
                }
#pragma unroll
            for (int m = 1; m < 4; m <<= 1)
#pragma unroll
                for (int mt = 0; mt < 2; mt++)
#pragma unroll
                    for (int h = 0; h < 2; h++) {
                        ps[mt][h] += __shfl_xor_sync(0xffffffffu, ps[mt][h], m);
                        pq[mt][h] += __shfl_xor_sync(0xffffffffu, pq[mt][h], m);
                    }
            if (tig == 0) {
#pragma unroll
                for (int mt = 0; mt < 2; mt++)
#pragma unroll
                    for (int h = 0; h < 2; h++) {
                        int r = wm * 32 + mt * 16 + g + 8 * h;
                        atomicAdd(&sSum[r], ps[mt][h]);
                        atomicAdd(&sSq[r], pq[mt][h]);
                    }
            }
            __syncthreads();
            const float* gS = sm + BIAS_F + 3 * H;
            const float* eS = sm + BIAS_F + 4 * H;
#pragma unroll
            for (int mt = 0; mt < 2; mt++)
#pragma unroll
                for (int h = 0; h < 2; h++) {
                    int r = wm * 32 + mt * 16 + g + 8 * h;
                    if (r >= nvalid) continue;
                    float mu = sSum[r] * (1.f / H);
                    float rs = rsqrtf(sSq[r] * (1.f / H) - mu * mu + 1e-5f);
                    size_t ro = (size_t)(base + r) * H;
                    int rc = (MODE == 1) ? sR[r] : 0;
#pragma unroll
                    for (int jj = 0; jj < 8; jj++) {
                        int n0 = wn * 64 + jj * 8 + 2 * tig;
                        float y0 = (c[mt * 8 + jj][2 * h] - mu) * rs * gS[n0] + eS[n0];
                        float y1 = (c[mt * 8 + jj][2 * h + 1] - mu) * rs * gS[n0 + 1] + eS[n0 + 1];
                        float2 rf = *(const float2*)(resid + ro + n0);
                        __stcs((float2*)(out + ro + n0), make_float2(y0 + rf.x, y1 + rf.y));
                        if (MODE == 1) red2(&acc[(size_t)rc * H + n0], y0, y1);
                    }
                }
        }
    }
}

// ============================ LAUNCH ============================
extern "C" void kernel_launch(void* const* d_in, const int* in_sizes, int n_in,
                              void* d_out, int out_size) {
    const int*   senders   = (const int*)d_in[0];
    const int*   receivers = (const int*)d_in[1];
    const float* nodef     = (const float*)d_in[2];
    const float* edgef     = (const float*)d_in[3];
    const float* eW0 = (const float*)d_in[4];
    const float* eb0 = (const float*)d_in[5];
    const float* eW1 = (const float*)d_in[6];
    const float* eb1 = (const float*)d_in[7];
    const float* eW2 = (const float*)d_in[8];
    const float* eb2 = (const float*)d_in[9];
    const float* eg  = (const float*)d_in[10];
    const float* ebeta = (const float*)d_in[11];
    const float* nW0 = (const float*)d_in[12];
    const float* nb0 = (const float*)d_in[13];
    const float* nW1 = (const float*)d_in[14];
    const float* nb1 = (const float*)d_in[15];
    const float* nW2 = (const float*)d_in[16];
    const float* nb2 = (const float*)d_in[17];
    const float* ng  = (const float*)d_in[18];
    const float* nbeta = (const float*)d_in[19];

    int E = in_sizes[1];
    int N = in_sizes[2] / H;

    float* out_node = (float*)d_out;
    float* out_edge = out_node + (size_t)N * H;

    float *acc = nullptr, *proj = nullptr;
    cudaGetSymbolAddress((void**)&acc, g_acc);
    cudaGetSymbolAddress((void**)&proj, g_proj);

    cudaFuncSetAttribute(gnb_kernel<0>, cudaFuncAttributeMaxDynamicSharedMemorySize, SMEM_BYTES);
    cudaFuncSetAttribute(gnb_kernel<1>, cudaFuncAttributeMaxDynamicSharedMemorySize, SMEM_BYTES);
    cudaFuncSetAttribute(gnb_kernel<2>, cudaFuncAttributeMaxDynamicSharedMemorySize, SMEM_BYTES);

    int ngrid = (N + TE - 1) / TE;
    int egrid = (E + TE - 1) / TE;

    // proj: P = nodef @ [eW0_send | eW0_recv | nW0_top]
    gnb_kernel<0><<<ngrid, THREADS, SMEM_BYTES>>>(
        nullptr, nullptr, nodef, nullptr, acc, proj,
        eW0, eW0 + (size_t)128 * H, nW0,
        eb0, eb0, eb0, eg, ebeta, nullptr, N);

    // edge MLP: ef @ eW0_bot (+gathered P) -> eW1 -> eW2 -> LN -> scatter
    gnb_kernel<1><<<egrid, THREADS, SMEM_BYTES>>>(
        senders, receivers, nodef, edgef, acc, proj,
        eW0 + (size_t)256 * H, eW1, eW2,
        eb0, eb1, eb2, eg, ebeta, out_edge, E);

    // node MLP: acc @ nW0_bot (+P nf-block) -> nW1 -> nW2 -> LN
    gnb_kernel<2><<<ngrid, THREADS, SMEM_BYTES>>>(
        nullptr, nullptr, nodef, nodef, acc, proj,
        nW0 + (size_t)128 * H, nW1, nW2,
        nb0, nb1, nb2, ng, nbeta, out_node, N);
}